// round 1
// baseline (speedup 1.0000x reference)
#include <cuda_runtime.h>
#include <math.h>

// Problem constants
#define Lc 2048
#define Hc 8
#define Bc 8
#define Sc 128
#define HSc 1024

// ---------------- scratch (device globals; no allocations allowed) ---------
__device__ float d_eT[Hc * Lc];       // e transposed: eT[h][d] = exp(W[d][h])
__device__ float d_zinv[Lc * Hc];     // 1/Z[l][h], Z = inclusive prefix sum of e over d
__device__ float d_q[Bc * HSc];       // raw q accumulator (pre-zinv scaling)
__device__ float d_u[Bc * HSc];       // u = (q*zinv_last) @ A
__device__ float d_G[Hc * Lc * Bc];   // G2[h][j][b]
__device__ float d_scores[Bc * Lc];   // scores[b][l] (l < L-1 valid)
__device__ float d_smax[Bc];
__device__ float d_sinv[Bc];

// ---------------- K0: zero accumulators + output ---------------------------
__global__ void k_zero(float* __restrict__ out) {
    int i = blockIdx.x * blockDim.x + threadIdx.x;   // grid covers 16384
    if (i < Bc * HSc) { d_q[i] = 0.f; d_u[i] = 0.f; }
    if (i < Bc * Lc)  d_scores[i] = 0.f;
    if (i < Bc * Sc)  out[i] = 0.f;
}

// ---------------- K1: e = exp(W), inclusive prefix sums -> zinv ------------
// grid = H blocks, 1024 threads; thread t owns d = 2t, 2t+1
__global__ void k_scan(const float* __restrict__ W) {
    int h = blockIdx.x;
    int t = threadIdx.x;
    float v0 = expf(W[(2 * t) * Hc + h]);
    float v1 = expf(W[(2 * t + 1) * Hc + h]);
    float s = v0 + v1;

    unsigned lane = t & 31, wid = t >> 5;
    float x = s;
    #pragma unroll
    for (int o = 1; o < 32; o <<= 1) {
        float y = __shfl_up_sync(0xffffffffu, x, o);
        if (lane >= (unsigned)o) x += y;
    }
    __shared__ float wsum[32];
    if (lane == 31) wsum[wid] = x;
    __syncthreads();
    if (wid == 0) {
        float ws = wsum[lane];
        #pragma unroll
        for (int o = 1; o < 32; o <<= 1) {
            float y = __shfl_up_sync(0xffffffffu, ws, o);
            if (lane >= (unsigned)o) ws += y;
        }
        wsum[lane] = ws;
    }
    __syncthreads();
    float warp_off = (wid == 0) ? 0.f : wsum[wid - 1];
    float incl = x + warp_off;       // inclusive through element 2t+1
    float excl = incl - s;
    d_eT[h * Lc + 2 * t]     = v0;
    d_eT[h * Lc + 2 * t + 1] = v1;
    d_zinv[(2 * t) * Hc + h]     = 1.f / (excl + v0);
    d_zinv[(2 * t + 1) * Hc + h] = 1.f / incl;
}

// ---------------- K2: q_raw[b][h*S+s] = sum_j e[L-1-j,h] * x[b,j,s] --------
// grid (L/128, B), block 128 (thread = s). Partial sums merged via atomics.
__global__ void __launch_bounds__(128) k_q(const float* __restrict__ x) {
    int jbase = blockIdx.x * 128;
    int b = blockIdx.y;
    int s = threadIdx.x;
    __shared__ __align__(16) float se[128 * 8];   // se[jj][h] = e[L-1-(jbase+jj)][h]
    for (int i = s; i < 128 * 8; i += 128) {
        int jj = i >> 3, h = i & 7;
        se[i] = d_eT[h * Lc + (Lc - 1 - (jbase + jj))];
    }
    __syncthreads();

    float a0=0,a1=0,a2=0,a3=0,a4=0,a5=0,a6=0,a7=0;
    const float* xp = x + ((size_t)b * Lc + jbase) * Sc + s;
    #pragma unroll 4
    for (int jj = 0; jj < 128; jj++) {
        float xv = xp[jj * Sc];
        float4 e0 = *(const float4*)&se[jj * 8];
        float4 e1 = *(const float4*)&se[jj * 8 + 4];
        a0 += e0.x * xv; a1 += e0.y * xv; a2 += e0.z * xv; a3 += e0.w * xv;
        a4 += e1.x * xv; a5 += e1.y * xv; a6 += e1.z * xv; a7 += e1.w * xv;
    }
    atomicAdd(&d_q[b * HSc + 0 * Sc + s], a0);
    atomicAdd(&d_q[b * HSc + 1 * Sc + s], a1);
    atomicAdd(&d_q[b * HSc + 2 * Sc + s], a2);
    atomicAdd(&d_q[b * HSc + 3 * Sc + s], a3);
    atomicAdd(&d_q[b * HSc + 4 * Sc + s], a4);
    atomicAdd(&d_q[b * HSc + 5 * Sc + s], a5);
    atomicAdd(&d_q[b * HSc + 6 * Sc + s], a6);
    atomicAdd(&d_q[b * HSc + 7 * Sc + s], a7);
}

// ---------------- K3: u[b][e] = sum_d (q[b][d]*zinv_last[h(d)]) * A[d][e] --
// grid (HS/128 e-chunks, HS/128 d-chunks), block 128 (thread = e)
__global__ void __launch_bounds__(128) k_u(const float* __restrict__ A) {
    int ebase = blockIdx.x * 128;
    int dbase = blockIdx.y * 128;
    int t = threadIdx.x;
    __shared__ __align__(16) float sq[128 * 8];   // sq[dd][b]
    for (int i = t; i < 128 * 8; i += 128) {
        int dd = i >> 3, b = i & 7;
        int d = dbase + dd;
        int h = d >> 7;
        sq[i] = d_q[b * HSc + d] * d_zinv[(Lc - 1) * Hc + h];
    }
    __syncthreads();

    int e = ebase + t;
    float a0=0,a1=0,a2=0,a3=0,a4=0,a5=0,a6=0,a7=0;
    const float* Ap = A + (size_t)dbase * HSc + e;
    #pragma unroll 4
    for (int dd = 0; dd < 128; dd++) {
        float av = Ap[dd * HSc];
        float4 q0 = *(const float4*)&sq[dd * 8];
        float4 q1 = *(const float4*)&sq[dd * 8 + 4];
        a0 += q0.x * av; a1 += q0.y * av; a2 += q0.z * av; a3 += q0.w * av;
        a4 += q1.x * av; a5 += q1.y * av; a6 += q1.z * av; a7 += q1.w * av;
    }
    atomicAdd(&d_u[0 * HSc + e], a0);
    atomicAdd(&d_u[1 * HSc + e], a1);
    atomicAdd(&d_u[2 * HSc + e], a2);
    atomicAdd(&d_u[3 * HSc + e], a3);
    atomicAdd(&d_u[4 * HSc + e], a4);
    atomicAdd(&d_u[5 * HSc + e], a5);
    atomicAdd(&d_u[6 * HSc + e], a6);
    atomicAdd(&d_u[7 * HSc + e], a7);
}

// ---------------- K4: G2[h][j][b] = sum_s u[b][h*S+s] * x[b][j][s] ---------
// grid (L/8, B), block 256 = 8 warps, warp w handles j = jbase + w
__global__ void __launch_bounds__(256) k_G(const float* __restrict__ x) {
    int b = blockIdx.y;
    int jbase = blockIdx.x * 8;
    int t = threadIdx.x;
    __shared__ __align__(16) float su[HSc];
    for (int i = t; i < HSc; i += 256) su[i] = d_u[b * HSc + i];
    __syncthreads();

    int w = t >> 5, lane = t & 31;
    int j = jbase + w;
    float4 xv = *(const float4*)(x + ((size_t)b * Lc + j) * Sc + lane * 4);
    float p[8];
    #pragma unroll
    for (int h = 0; h < 8; h++) {
        float4 uv = *(const float4*)&su[h * Sc + lane * 4];
        p[h] = uv.x * xv.x + uv.y * xv.y + uv.z * xv.z + uv.w * xv.w;
    }
    #pragma unroll
    for (int o = 16; o >= 1; o >>= 1) {
        #pragma unroll
        for (int h = 0; h < 8; h++)
            p[h] += __shfl_xor_sync(0xffffffffu, p[h], o);
    }
    // lane i < 8 writes G2[i][j][b]
    float v = p[0];
    #pragma unroll
    for (int h = 1; h < 8; h++) v = (lane == h) ? p[h] : v;
    if (lane < 8)
        d_G[(size_t)lane * Lc * Bc + j * Bc + b] = v;
}

// ---------------- K5: Toeplitz causal correlation (dominant) ---------------
// scores[b,l] += zinv[l,h] * sum_{j<=l} e[l-j,h] * G2[h][j][b]
// grid (16 ltiles, 4 jgroups, 8 h), block 128 = 4 warps.
// Warp w covers jj in [w*32, w*32+32) for each jtile in its group of 4.
// Thread tile: 4 l-values (lane, lane+32, lane+64, lane+96) x 8 b.
__global__ void __launch_bounds__(128) k_scores() {
    int lt = blockIdx.x, jg = blockIdx.y, h = blockIdx.z;
    int jt0 = jg * 4;
    if (jt0 > lt) return;
    int jt1 = min(jt0 + 4, lt + 1);
    int lbase = lt * 128;
    int t = threadIdx.x, w = t >> 5, lane = t & 31;

    float acc[4][8] = {};
    const float* eTh = d_eT + (size_t)h * Lc;
    const float* Gh  = d_G + (size_t)h * Lc * Bc;

    for (int jt = jt0; jt < jt1; jt++) {
        int jb = jt * 128 + w * 32;
        if (jt < lt) {
            #pragma unroll 2
            for (int jj = 0; jj < 32; jj++) {
                int j = jb + jj;
                float4 g0 = *(const float4*)(Gh + j * 8);
                float4 g1 = *(const float4*)(Gh + j * 8 + 4);
                const float* ep = eTh + (lbase + lane - j);
                #pragma unroll
                for (int k = 0; k < 4; k++) {
                    float ev = ep[32 * k];
                    acc[k][0] += ev * g0.x; acc[k][1] += ev * g0.y;
                    acc[k][2] += ev * g0.z; acc[k][3] += ev * g0.w;
                    acc[k][4] += ev * g1.x; acc[k][5] += ev * g1.y;
                    acc[k][6] += ev * g1.z; acc[k][7] += ev * g1.w;
                }
            }
        } else {  // diagonal tile: guard d >= 0
            for (int jj = 0; jj < 32; jj++) {
                int j = jb + jj;
                float4 g0 = *(const float4*)(Gh + j * 8);
                float4 g1 = *(const float4*)(Gh + j * 8 + 4);
                int dbase = lbase + lane - j;
                #pragma unroll
                for (int k = 0; k < 4; k++) {
                    int d = dbase + 32 * k;
                    float ev = (d >= 0) ? eTh[d] : 0.f;
                    acc[k][0] += ev * g0.x; acc[k][1] += ev * g0.y;
                    acc[k][2] += ev * g0.z; acc[k][3] += ev * g0.w;
                    acc[k][4] += ev * g1.x; acc[k][5] += ev * g1.y;
                    acc[k][6] += ev * g1.z; acc[k][7] += ev * g1.w;
                }
            }
        }
    }

    __shared__ __align__(16) float sacc[4][128][8];
    #pragma unroll
    for (int k = 0; k < 4; k++) {
        *(float4*)&sacc[w][lane + 32 * k][0] = make_float4(acc[k][0], acc[k][1], acc[k][2], acc[k][3]);
        *(float4*)&sacc[w][lane + 32 * k][4] = make_float4(acc[k][4], acc[k][5], acc[k][6], acc[k][7]);
    }
    __syncthreads();

    int l = lbase + t;
    if (l < Lc - 1) {
        float zi = d_zinv[l * Hc + h];
        #pragma unroll
        for (int b = 0; b < 8; b++) {
            float v = sacc[0][t][b] + sacc[1][t][b] + sacc[2][t][b] + sacc[3][t][b];
            atomicAdd(&d_scores[b * Lc + l], v * zi);
        }
    }
}

// ---------------- K6a: softmax stats over scores[b][0..L-2] ----------------
__global__ void __launch_bounds__(256) k_stats() {
    int b = blockIdx.x, t = threadIdx.x;
    __shared__ float red[256];
    float m = -1e30f;
    for (int l = t; l < Lc - 1; l += 256) m = fmaxf(m, d_scores[b * Lc + l]);
    red[t] = m; __syncthreads();
    for (int o = 128; o > 0; o >>= 1) {
        if (t < o) red[t] = fmaxf(red[t], red[t + o]);
        __syncthreads();
    }
    float M = red[0]; __syncthreads();
    float s = 0.f;
    for (int l = t; l < Lc - 1; l += 256) s += expf(d_scores[b * Lc + l] - M);
    red[t] = s; __syncthreads();
    for (int o = 128; o > 0; o >>= 1) {
        if (t < o) red[t] += red[t + o];
        __syncthreads();
    }
    if (t == 0) { d_smax[b] = M; d_sinv[b] = 1.f / red[0]; }
}

// ---------------- K6b: out[b][s] = sum_l w2[b,l] * x[b,l,s] ----------------
// grid (L/128, B), block 128 (thread = s)
__global__ void __launch_bounds__(128) k_out(const float* __restrict__ x,
                                             float* __restrict__ out) {
    int lbase = blockIdx.x * 128;
    int b = blockIdx.y;
    int s = threadIdx.x;
    __shared__ float wsm[128];
    int lg = lbase + s;
    wsm[s] = (lg < Lc - 1) ? expf(d_scores[b * Lc + lg] - d_smax[b]) * d_sinv[b] : 0.f;
    __syncthreads();
    float acc = 0.f;
    const float* xp = x + ((size_t)b * Lc + lbase) * Sc + s;
    #pragma unroll 4
    for (int jj = 0; jj < 128; jj++) acc += wsm[jj] * xp[jj * Sc];
    atomicAdd(&out[b * Sc + s], acc);
}

// ---------------- launch ----------------------------------------------------
extern "C" void kernel_launch(void* const* d_in, const int* in_sizes, int n_in,
                              void* d_out, int out_size) {
    const float *x = nullptr, *W = nullptr, *A = nullptr;
    for (int i = 0; i < n_in; i++) {
        if (in_sizes[i] == Bc * Lc * Sc)      x = (const float*)d_in[i];
        else if (in_sizes[i] == Lc * Hc)      W = (const float*)d_in[i];
        else if (in_sizes[i] == HSc * HSc)    A = (const float*)d_in[i];
    }
    float* out = (float*)d_out;

    k_zero<<<64, 256>>>(out);
    k_scan<<<Hc, 1024>>>(W);
    k_q<<<dim3(Lc / 128, Bc), 128>>>(x);
    k_u<<<dim3(HSc / 128, HSc / 128), 128>>>(A);
    k_G<<<dim3(Lc / 8, Bc), 256>>>(x);
    k_scores<<<dim3(Lc / 128, 4, Hc), 128>>>();
    k_stats<<<Bc, 256>>>();
    k_out<<<dim3(Lc / 128, Bc), 128>>>(x, out);
}

// round 2
// speedup vs baseline: 1.3325x; 1.3325x over previous
#include <cuda_runtime.h>
#include <math.h>

// Problem constants
#define Lc 2048
#define Hc 8
#define Bc 8
#define Sc 128
#define HSc 1024

// ---------------- scratch (device globals; no allocations allowed) ---------
__device__ float d_eT[Hc * Lc];       // e transposed: eT[h][d] = exp(W[d][h])
__device__ float d_zinv[Lc * Hc];     // 1/Z[l][h]
__device__ float d_q[Bc * HSc];       // raw q accumulator (pre-zinv scaling)
__device__ float d_u[Bc * HSc];       // u = (q*zinv_last) @ A
__device__ float d_G[Hc * Lc * Bc];   // G2[h][j][b]
__device__ float d_scores[Bc * Lc];   // scores[b][l] (l < L-1 valid)
__device__ float d_smax[Bc];
__device__ float d_sinv[Bc];

// f32x2 packed helpers (PTX ISA 8.6, sm_100+)
__device__ __forceinline__ unsigned long long pack2(float v) {
    unsigned long long r;
    asm("mov.b64 %0, {%1, %1};" : "=l"(r) : "f"(v));
    return r;
}
__device__ __forceinline__ void fma2(unsigned long long& acc,
                                     unsigned long long a, unsigned long long b) {
    asm("fma.rn.f32x2 %0, %1, %2, %0;" : "+l"(acc) : "l"(a), "l"(b));
}
__device__ __forceinline__ float2 unpack2(unsigned long long v) {
    float2 r;
    asm("mov.b64 {%0, %1}, %2;" : "=f"(r.x), "=f"(r.y) : "l"(v));
    return r;
}

// ---------------- K0: zero accumulators + output ---------------------------
__global__ void k_zero(float* __restrict__ out) {
    int i = blockIdx.x * blockDim.x + threadIdx.x;   // grid covers 16384
    if (i < Bc * HSc) { d_q[i] = 0.f; d_u[i] = 0.f; }
    if (i < Bc * Lc)  d_scores[i] = 0.f;
    if (i < Bc * Sc)  out[i] = 0.f;
}

// ---------------- K1: e = exp(W), inclusive prefix sums -> zinv ------------
__global__ void k_scan(const float* __restrict__ W) {
    int h = blockIdx.x;
    int t = threadIdx.x;
    float v0 = expf(W[(2 * t) * Hc + h]);
    float v1 = expf(W[(2 * t + 1) * Hc + h]);
    float s = v0 + v1;

    unsigned lane = t & 31, wid = t >> 5;
    float x = s;
    #pragma unroll
    for (int o = 1; o < 32; o <<= 1) {
        float y = __shfl_up_sync(0xffffffffu, x, o);
        if (lane >= (unsigned)o) x += y;
    }
    __shared__ float wsum[32];
    if (lane == 31) wsum[wid] = x;
    __syncthreads();
    if (wid == 0) {
        float ws = wsum[lane];
        #pragma unroll
        for (int o = 1; o < 32; o <<= 1) {
            float y = __shfl_up_sync(0xffffffffu, ws, o);
            if (lane >= (unsigned)o) ws += y;
        }
        wsum[lane] = ws;
    }
    __syncthreads();
    float warp_off = (wid == 0) ? 0.f : wsum[wid - 1];
    float incl = x + warp_off;
    float excl = incl - s;
    d_eT[h * Lc + 2 * t]     = v0;
    d_eT[h * Lc + 2 * t + 1] = v1;
    d_zinv[(2 * t) * Hc + h]     = 1.f / (excl + v0);
    d_zinv[(2 * t + 1) * Hc + h] = 1.f / incl;
}

// ---------------- K2: q_raw[b][h*S+s] = sum_j e[L-1-j,h] * x[b,j,s] --------
// grid (L/64, B), block 128 (thread = s). Batch-8 loads for MLP.
__global__ void __launch_bounds__(128) k_q(const float* __restrict__ x) {
    int jbase = blockIdx.x * 64;
    int b = blockIdx.y;
    int s = threadIdx.x;
    __shared__ __align__(16) float se[64 * 8];   // se[jj][h]
    for (int i = s; i < 64 * 8; i += 128) {
        int jj = i >> 3, h = i & 7;
        se[i] = d_eT[h * Lc + (Lc - 1 - (jbase + jj))];
    }
    __syncthreads();

    float a[8] = {};
    const float* xp = x + ((size_t)b * Lc + jbase) * Sc + s;
    #pragma unroll
    for (int j0 = 0; j0 < 64; j0 += 8) {
        float xv[8];
        #pragma unroll
        for (int k = 0; k < 8; k++) xv[k] = xp[(j0 + k) * Sc];
        #pragma unroll
        for (int k = 0; k < 8; k++) {
            float4 e0 = *(const float4*)&se[(j0 + k) * 8];
            float4 e1 = *(const float4*)&se[(j0 + k) * 8 + 4];
            a[0] += e0.x * xv[k]; a[1] += e0.y * xv[k];
            a[2] += e0.z * xv[k]; a[3] += e0.w * xv[k];
            a[4] += e1.x * xv[k]; a[5] += e1.y * xv[k];
            a[6] += e1.z * xv[k]; a[7] += e1.w * xv[k];
        }
    }
    #pragma unroll
    for (int h = 0; h < 8; h++)
        atomicAdd(&d_q[b * HSc + h * Sc + s], a[h]);
}

// ---------------- K3: u[b][e] = sum_d (q[b][d]*zinv_last) * A[d][e] --------
// grid (HS/256 e-chunks, 32 d-chunks of 32), block 256 (thread = e).
__global__ void __launch_bounds__(256) k_u(const float* __restrict__ A) {
    int ebase = blockIdx.x * 256;
    int dbase = blockIdx.y * 32;
    int t = threadIdx.x;
    __shared__ __align__(16) float sq[32 * 8];   // sq[dd][b]
    {
        int dd = t >> 3, b = t & 7;
        int d = dbase + dd;
        sq[t] = d_q[b * HSc + d] * d_zinv[(Lc - 1) * Hc + (d >> 7)];
    }
    __syncthreads();

    int e = ebase + t;
    float a[8] = {};
    const float* Ap = A + (size_t)dbase * HSc + e;
    #pragma unroll
    for (int d0 = 0; d0 < 32; d0 += 8) {
        float av[8];
        #pragma unroll
        for (int k = 0; k < 8; k++) av[k] = Ap[(d0 + k) * HSc];
        #pragma unroll
        for (int k = 0; k < 8; k++) {
            float4 q0 = *(const float4*)&sq[(d0 + k) * 8];
            float4 q1 = *(const float4*)&sq[(d0 + k) * 8 + 4];
            a[0] += q0.x * av[k]; a[1] += q0.y * av[k];
            a[2] += q0.z * av[k]; a[3] += q0.w * av[k];
            a[4] += q1.x * av[k]; a[5] += q1.y * av[k];
            a[6] += q1.z * av[k]; a[7] += q1.w * av[k];
        }
    }
    #pragma unroll
    for (int b = 0; b < 8; b++)
        atomicAdd(&d_u[b * HSc + e], a[b]);
}

// ---------------- K4: G2[h][j][b] = sum_s u[b][h*S+s] * x[b][j][s] ---------
__global__ void __launch_bounds__(256) k_G(const float* __restrict__ x) {
    int b = blockIdx.y;
    int jbase = blockIdx.x * 8;
    int t = threadIdx.x;
    __shared__ __align__(16) float su[HSc];
    for (int i = t; i < HSc; i += 256) su[i] = d_u[b * HSc + i];
    __syncthreads();

    int w = t >> 5, lane = t & 31;
    int j = jbase + w;
    float4 xv = *(const float4*)(x + ((size_t)b * Lc + j) * Sc + lane * 4);
    float p[8];
    #pragma unroll
    for (int h = 0; h < 8; h++) {
        float4 uv = *(const float4*)&su[h * Sc + lane * 4];
        p[h] = uv.x * xv.x + uv.y * xv.y + uv.z * xv.z + uv.w * xv.w;
    }
    #pragma unroll
    for (int o = 16; o >= 1; o >>= 1) {
        #pragma unroll
        for (int h = 0; h < 8; h++)
            p[h] += __shfl_xor_sync(0xffffffffu, p[h], o);
    }
    float v = p[0];
    #pragma unroll
    for (int h = 1; h < 8; h++) v = (lane == h) ? p[h] : v;
    if (lane < 8)
        d_G[(size_t)lane * Lc * Bc + j * Bc + b] = v;
}

// ---------------- K5: Toeplitz causal correlation (dominant) ---------------
// scores[b,l] += zinv[l,h] * sum_{j<=l} e[l-j,h] * G2[h][j][b]
// Packed f32x2 accumulators: b-pairs (0,1)(2,3)(4,5)(6,7).
__global__ void __launch_bounds__(128) k_scores() {
    int lt = blockIdx.x, jg = blockIdx.y, h = blockIdx.z;
    int jt0 = jg * 4;
    if (jt0 > lt) return;
    int jt1 = min(jt0 + 4, lt + 1);
    int lbase = lt * 128;
    int t = threadIdx.x, w = t >> 5, lane = t & 31;

    unsigned long long acc[4][4] = {};   // [k][b-pair]
    const float* eTh = d_eT + (size_t)h * Lc;
    const float* Gh  = d_G + (size_t)h * Lc * Bc;

    for (int jt = jt0; jt < jt1; jt++) {
        int jb = jt * 128 + w * 32;
        if (jt < lt) {
            #pragma unroll 2
            for (int jj = 0; jj < 32; jj++) {
                int j = jb + jj;
                ulonglong2 g01 = *(const ulonglong2*)(Gh + j * 8);
                ulonglong2 g23 = *(const ulonglong2*)(Gh + j * 8 + 4);
                const float* ep = eTh + (lbase + lane - j);
                #pragma unroll
                for (int k = 0; k < 4; k++) {
                    unsigned long long ev = pack2(ep[32 * k]);
                    fma2(acc[k][0], ev, g01.x);
                    fma2(acc[k][1], ev, g01.y);
                    fma2(acc[k][2], ev, g23.x);
                    fma2(acc[k][3], ev, g23.y);
                }
            }
        } else {  // diagonal tile: guard d >= 0
            for (int jj = 0; jj < 32; jj++) {
                int j = jb + jj;
                ulonglong2 g01 = *(const ulonglong2*)(Gh + j * 8);
                ulonglong2 g23 = *(const ulonglong2*)(Gh + j * 8 + 4);
                int dbase = lbase + lane - j;
                #pragma unroll
                for (int k = 0; k < 4; k++) {
                    int d = dbase + 32 * k;
                    unsigned long long ev = pack2((d >= 0) ? eTh[d] : 0.f);
                    fma2(acc[k][0], ev, g01.x);
                    fma2(acc[k][1], ev, g01.y);
                    fma2(acc[k][2], ev, g23.x);
                    fma2(acc[k][3], ev, g23.y);
                }
            }
        }
    }

    __shared__ __align__(16) float sacc[4][128][8];
    #pragma unroll
    for (int k = 0; k < 4; k++) {
        float2 p0 = unpack2(acc[k][0]);
        float2 p1 = unpack2(acc[k][1]);
        float2 p2 = unpack2(acc[k][2]);
        float2 p3 = unpack2(acc[k][3]);
        *(float4*)&sacc[w][lane + 32 * k][0] = make_float4(p0.x, p0.y, p1.x, p1.y);
        *(float4*)&sacc[w][lane + 32 * k][4] = make_float4(p2.x, p2.y, p3.x, p3.y);
    }
    __syncthreads();

    int l = lbase + t;
    if (l < Lc - 1) {
        float zi = d_zinv[l * Hc + h];
        #pragma unroll
        for (int b = 0; b < 8; b++) {
            float v = sacc[0][t][b] + sacc[1][t][b] + sacc[2][t][b] + sacc[3][t][b];
            atomicAdd(&d_scores[b * Lc + l], v * zi);
        }
    }
}

// ---------------- K6a: softmax stats over scores[b][0..L-2] ----------------
__global__ void __launch_bounds__(256) k_stats() {
    int b = blockIdx.x, t = threadIdx.x;
    __shared__ float red[256];
    float m = -1e30f;
    for (int l = t; l < Lc - 1; l += 256) m = fmaxf(m, d_scores[b * Lc + l]);
    red[t] = m; __syncthreads();
    for (int o = 128; o > 0; o >>= 1) {
        if (t < o) red[t] = fmaxf(red[t], red[t + o]);
        __syncthreads();
    }
    float M = red[0]; __syncthreads();
    float s = 0.f;
    for (int l = t; l < Lc - 1; l += 256) s += expf(d_scores[b * Lc + l] - M);
    red[t] = s; __syncthreads();
    for (int o = 128; o > 0; o >>= 1) {
        if (t < o) red[t] += red[t + o];
        __syncthreads();
    }
    if (t == 0) { d_smax[b] = M; d_sinv[b] = 1.f / red[0]; }
}

// ---------------- K6b: out[b][s] = sum_l w2[b,l] * x[b,l,s] ----------------
// grid (L/64, B), block 128 (thread = s). Batch-8 loads.
__global__ void __launch_bounds__(128) k_out(const float* __restrict__ x,
                                             float* __restrict__ out) {
    int lbase = blockIdx.x * 64;
    int b = blockIdx.y;
    int s = threadIdx.x;
    __shared__ float wsm[64];
    if (s < 64) {
        int lg = lbase + s;
        wsm[s] = (lg < Lc - 1) ? expf(d_scores[b * Lc + lg] - d_smax[b]) * d_sinv[b] : 0.f;
    }
    __syncthreads();
    float acc = 0.f;
    const float* xp = x + ((size_t)b * Lc + lbase) * Sc + s;
    #pragma unroll
    for (int j0 = 0; j0 < 64; j0 += 8) {
        float xv[8];
        #pragma unroll
        for (int k = 0; k < 8; k++) xv[k] = xp[(j0 + k) * Sc];
        #pragma unroll
        for (int k = 0; k < 8; k++) acc += wsm[j0 + k] * xv[k];
    }
    atomicAdd(&out[b * Sc + s], acc);
}

// ---------------- launch ----------------------------------------------------
extern "C" void kernel_launch(void* const* d_in, const int* in_sizes, int n_in,
                              void* d_out, int out_size) {
    const float *x = nullptr, *W = nullptr, *A = nullptr;
    for (int i = 0; i < n_in; i++) {
        if (in_sizes[i] == Bc * Lc * Sc)      x = (const float*)d_in[i];
        else if (in_sizes[i] == Lc * Hc)      W = (const float*)d_in[i];
        else if (in_sizes[i] == HSc * HSc)    A = (const float*)d_in[i];
    }
    float* out = (float*)d_out;

    k_zero<<<64, 256>>>(out);
    k_scan<<<Hc, 1024>>>(W);
    k_q<<<dim3(Lc / 64, Bc), 128>>>(x);
    k_u<<<dim3(HSc / 256, 32), 256>>>(A);
    k_G<<<dim3(Lc / 8, Bc), 256>>>(x);
    k_scores<<<dim3(Lc / 128, 4, Hc), 128>>>();
    k_stats<<<Bc, 256>>>();
    k_out<<<dim3(Lc / 64, Bc), 128>>>(x, out);
}

// round 3
// speedup vs baseline: 1.3776x; 1.0339x over previous
#include <cuda_runtime.h>
#include <math.h>

// Problem constants
#define Lc 2048
#define Hc 8
#define Bc 8
#define Sc 128
#define HSc 1024

// ---------------- scratch (device globals) ----------------------------------
__device__ float d_eT[Hc * Lc];       // eT[h][d] = exp(W[d][h])
__device__ float d_zinv[Lc * Hc];     // 1/Z[l][h]
__device__ float d_q[Bc * HSc];
__device__ float d_u[Bc * HSc];
__device__ float d_G[Hc * Lc * Bc];   // G2[h][j][b]
__device__ float d_scores[Bc * Lc];

// f32x2 packed helpers (sm_100+)
__device__ __forceinline__ unsigned long long pack2(float v) {
    unsigned long long r;
    asm("mov.b64 %0, {%1, %1};" : "=l"(r) : "f"(v));
    return r;
}
__device__ __forceinline__ void fma2(unsigned long long& acc,
                                     unsigned long long a, unsigned long long b) {
    asm("fma.rn.f32x2 %0, %1, %2, %0;" : "+l"(acc) : "l"(a), "l"(b));
}
__device__ __forceinline__ float2 unpack2(unsigned long long v) {
    float2 r;
    asm("mov.b64 {%0, %1}, %2;" : "=f"(r.x), "=f"(r.y) : "l"(v));
    return r;
}

// ---------------- K0: init = scan (blocks 0..7) + zero (blocks 8..23) ------
__global__ void __launch_bounds__(1024) k_init(const float* __restrict__ W,
                                               float* __restrict__ out) {
    int blk = blockIdx.x;
    int t = threadIdx.x;
    if (blk < 8) {
        int h = blk;
        float v0 = expf(W[(2 * t) * Hc + h]);
        float v1 = expf(W[(2 * t + 1) * Hc + h]);
        float s = v0 + v1;
        unsigned lane = t & 31, wid = t >> 5;
        float x = s;
        #pragma unroll
        for (int o = 1; o < 32; o <<= 1) {
            float y = __shfl_up_sync(0xffffffffu, x, o);
            if (lane >= (unsigned)o) x += y;
        }
        __shared__ float wsum[32];
        if (lane == 31) wsum[wid] = x;
        __syncthreads();
        if (wid == 0) {
            float ws = wsum[lane];
            #pragma unroll
            for (int o = 1; o < 32; o <<= 1) {
                float y = __shfl_up_sync(0xffffffffu, ws, o);
                if (lane >= (unsigned)o) ws += y;
            }
            wsum[lane] = ws;
        }
        __syncthreads();
        float warp_off = (wid == 0) ? 0.f : wsum[wid - 1];
        float incl = x + warp_off;
        float excl = incl - s;
        d_eT[h * Lc + 2 * t]     = v0;
        d_eT[h * Lc + 2 * t + 1] = v1;
        d_zinv[(2 * t) * Hc + h]     = 1.f / (excl + v0);
        d_zinv[(2 * t + 1) * Hc + h] = 1.f / incl;
    } else {
        int i = (blk - 8) * 1024 + t;
        if (i < Bc * HSc) { d_q[i] = 0.f; d_u[i] = 0.f; }
        if (i < Bc * Lc)  d_scores[i] = 0.f;
        if (i < Bc * Sc)  out[i] = 0.f;
    }
}

// ---------------- K1: q_raw[b][h*S+s] = sum_j e[L-1-j,h] * x[b,j,s] --------
// grid (L/64, B), block 128 (thread = s). Batch-16 loads for MLP.
__global__ void __launch_bounds__(128) k_q(const float* __restrict__ x) {
    int jbase = blockIdx.x * 64;
    int b = blockIdx.y;
    int s = threadIdx.x;
    __shared__ __align__(16) float se[64 * 8];   // se[jj][h]
    for (int i = s; i < 64 * 8; i += 128) {
        int jj = i >> 3, h = i & 7;
        se[i] = d_eT[h * Lc + (Lc - 1 - (jbase + jj))];
    }
    __syncthreads();

    float a[8] = {};
    const float* xp = x + ((size_t)b * Lc + jbase) * Sc + s;
    #pragma unroll
    for (int j0 = 0; j0 < 64; j0 += 16) {
        float xv[16];
        #pragma unroll
        for (int k = 0; k < 16; k++) xv[k] = xp[(j0 + k) * Sc];
        #pragma unroll
        for (int k = 0; k < 16; k++) {
            float4 e0 = *(const float4*)&se[(j0 + k) * 8];
            float4 e1 = *(const float4*)&se[(j0 + k) * 8 + 4];
            a[0] += e0.x * xv[k]; a[1] += e0.y * xv[k];
            a[2] += e0.z * xv[k]; a[3] += e0.w * xv[k];
            a[4] += e1.x * xv[k]; a[5] += e1.y * xv[k];
            a[6] += e1.z * xv[k]; a[7] += e1.w * xv[k];
        }
    }
    #pragma unroll
    for (int h = 0; h < 8; h++)
        atomicAdd(&d_q[b * HSc + h * Sc + s], a[h]);
}

// ---------------- K2: u[b][e] = sum_d (q[b][d]*zinv_last) * A[d][e] --------
// grid (4 e-chunks, 64 d-chunks of 16), block 256 (thread = e). Batch-16.
__global__ void __launch_bounds__(256) k_u(const float* __restrict__ A) {
    int ebase = blockIdx.x * 256;
    int dbase = blockIdx.y * 16;
    int t = threadIdx.x;
    __shared__ __align__(16) float sq[16 * 8];   // sq[dd][b]
    if (t < 128) {
        int dd = t >> 3, b = t & 7;
        int d = dbase + dd;
        sq[t] = d_q[b * HSc + d] * d_zinv[(Lc - 1) * Hc + (d >> 7)];
    }
    __syncthreads();

    int e = ebase + t;
    float a[8] = {};
    const float* Ap = A + (size_t)dbase * HSc + e;
    float av[16];
    #pragma unroll
    for (int k = 0; k < 16; k++) av[k] = Ap[k * HSc];
    #pragma unroll
    for (int k = 0; k < 16; k++) {
        float4 q0 = *(const float4*)&sq[k * 8];
        float4 q1 = *(const float4*)&sq[k * 8 + 4];
        a[0] += q0.x * av[k]; a[1] += q0.y * av[k];
        a[2] += q0.z * av[k]; a[3] += q0.w * av[k];
        a[4] += q1.x * av[k]; a[5] += q1.y * av[k];
        a[6] += q1.z * av[k]; a[7] += q1.w * av[k];
    }
    #pragma unroll
    for (int b = 0; b < 8; b++)
        atomicAdd(&d_u[b * HSc + e], a[b]);
}

// ---------------- K3: G2[h][j][b] = sum_s u[b][h*S+s] * x[b][j][s] ---------
__global__ void __launch_bounds__(256) k_G(const float* __restrict__ x) {
    int b = blockIdx.y;
    int jbase = blockIdx.x * 8;
    int t = threadIdx.x;
    __shared__ __align__(16) float su[HSc];
    for (int i = t; i < HSc; i += 256) su[i] = d_u[b * HSc + i];
    __syncthreads();

    int w = t >> 5, lane = t & 31;
    int j = jbase + w;
    float4 xv = *(const float4*)(x + ((size_t)b * Lc + j) * Sc + lane * 4);
    float p[8];
    #pragma unroll
    for (int h = 0; h < 8; h++) {
        float4 uv = *(const float4*)&su[h * Sc + lane * 4];
        p[h] = uv.x * xv.x + uv.y * xv.y + uv.z * xv.z + uv.w * xv.w;
    }
    #pragma unroll
    for (int o = 16; o >= 1; o >>= 1) {
        #pragma unroll
        for (int h = 0; h < 8; h++)
            p[h] += __shfl_xor_sync(0xffffffffu, p[h], o);
    }
    float v = p[0];
    #pragma unroll
    for (int h = 1; h < 8; h++) v = (lane == h) ? p[h] : v;
    if (lane < 8)
        d_G[(size_t)lane * Lc * Bc + j * Bc + b] = v;
}

// ---------------- K4: Toeplitz causal correlation (dominant) ---------------
// scores[b,l] += zinv[l,h] * sum_{j<=l} e[l-j,h] * G2[h][j][b]
// eT window staged in smem (zero-padded for d<0) -> branch-free inner loop.
__global__ void __launch_bounds__(128) k_scores() {
    int lt = blockIdx.x, jg = blockIdx.y, h = blockIdx.z;
    int jt0 = jg * 4;
    if (jt0 > lt) return;
    int jt1 = min(jt0 + 4, lt + 1);
    int lbase = lt * 128;
    int t = threadIdx.x, w = t >> 5, lane = t & 31;

    unsigned long long acc[4][4] = {};   // [k][b-pair]
    const float* eTh = d_eT + (size_t)h * Lc;
    const float* Gh  = d_G + (size_t)h * Lc * Bc;

    __shared__ __align__(16) float se[256];

    for (int jt = jt0; jt < jt1; jt++) {
        int D0 = lbase - jt * 128;          // >= 0
        // stage eT[D0-127 .. D0+128), zero-padded below 0
        __syncthreads();
        {
            int i0 = t, i1 = t + 128;
            int d0 = D0 - 127 + i0, d1 = D0 - 127 + i1;
            se[i0] = (d0 >= 0) ? eTh[d0] : 0.f;
            se[i1] = (d1 >= 0) ? eTh[d1] : 0.f;
        }
        __syncthreads();

        int jb = jt * 128 + w * 32;
        // idx into se: 127 + (lane + 32k) - (w*32 + jj)
        int base_idx = 127 + lane - w * 32;
        #pragma unroll 2
        for (int jj = 0; jj < 32; jj++) {
            int j = jb + jj;
            ulonglong2 g01 = *(const ulonglong2*)(Gh + j * 8);
            ulonglong2 g23 = *(const ulonglong2*)(Gh + j * 8 + 4);
            int bi = base_idx - jj;
            #pragma unroll
            for (int k = 0; k < 4; k++) {
                unsigned long long ev = pack2(se[bi + 32 * k]);
                fma2(acc[k][0], ev, g01.x);
                fma2(acc[k][1], ev, g01.y);
                fma2(acc[k][2], ev, g23.x);
                fma2(acc[k][3], ev, g23.y);
            }
        }
    }

    __shared__ __align__(16) float sacc[4][128][8];
    #pragma unroll
    for (int k = 0; k < 4; k++) {
        float2 p0 = unpack2(acc[k][0]);
        float2 p1 = unpack2(acc[k][1]);
        float2 p2 = unpack2(acc[k][2]);
        float2 p3 = unpack2(acc[k][3]);
        *(float4*)&sacc[w][lane + 32 * k][0] = make_float4(p0.x, p0.y, p1.x, p1.y);
        *(float4*)&sacc[w][lane + 32 * k][4] = make_float4(p2.x, p2.y, p3.x, p3.y);
    }
    __syncthreads();

    int l = lbase + t;
    if (l < Lc - 1) {
        float zi = d_zinv[l * Hc + h];
        #pragma unroll
        for (int b = 0; b < 8; b++) {
            float v = sacc[0][t][b] + sacc[1][t][b] + sacc[2][t][b] + sacc[3][t][b];
            atomicAdd(&d_scores[b * Lc + l], v * zi);
        }
    }
}

// ---------------- K5: fused softmax stats + out ------------------------------
// grid (L/64, B), block 128. Each block redundantly computes stats for its b.
__global__ void __launch_bounds__(128) k_out(const float* __restrict__ x,
                                             float* __restrict__ out) {
    int lbase = blockIdx.x * 64;
    int b = blockIdx.y;
    int t = threadIdx.x;
    const float* sc = d_scores + b * Lc;

    __shared__ float red[128];
    // max
    float m = -1e30f;
    for (int l = t; l < Lc - 1; l += 128) m = fmaxf(m, sc[l]);
    red[t] = m; __syncthreads();
    for (int o = 64; o > 0; o >>= 1) {
        if (t < o) red[t] = fmaxf(red[t], red[t + o]);
        __syncthreads();
    }
    float M = red[0]; __syncthreads();
    // sum
    float ss = 0.f;
    for (int l = t; l < Lc - 1; l += 128) ss += expf(sc[l] - M);
    red[t] = ss; __syncthreads();
    for (int o = 64; o > 0; o >>= 1) {
        if (t < o) red[t] += red[t + o];
        __syncthreads();
    }
    float sinv = 1.f / red[0];
    __syncthreads();

    __shared__ float wsm[64];
    if (t < 64) {
        int lg = lbase + t;
        wsm[t] = (lg < Lc - 1) ? expf(sc[lg] - M) * sinv : 0.f;
    }
    __syncthreads();

    float acc = 0.f;
    const float* xp = x + ((size_t)b * Lc + lbase) * Sc + t;
    #pragma unroll
    for (int j0 = 0; j0 < 64; j0 += 16) {
        float xv[16];
        #pragma unroll
        for (int k = 0; k < 16; k++) xv[k] = xp[(j0 + k) * Sc];
        #pragma unroll
        for (int k = 0; k < 16; k++) acc += wsm[j0 + k] * xv[k];
    }
    atomicAdd(&out[b * Sc + t], acc);
}

// ---------------- launch ----------------------------------------------------
extern "C" void kernel_launch(void* const* d_in, const int* in_sizes, int n_in,
                              void* d_out, int out_size) {
    const float *x = nullptr, *W = nullptr, *A = nullptr;
    for (int i = 0; i < n_in; i++) {
        if (in_sizes[i] == Bc * Lc * Sc)      x = (const float*)d_in[i];
        else if (in_sizes[i] == Lc * Hc)      W = (const float*)d_in[i];
        else if (in_sizes[i] == HSc * HSc)    A = (const float*)d_in[i];
    }
    float* out = (float*)d_out;

    k_init<<<24, 1024>>>(W, out);
    k_q<<<dim3(Lc / 64, Bc), 128>>>(x);
    k_u<<<dim3(HSc / 256, 64), 256>>>(A);
    k_G<<<dim3(Lc / 8, Bc), 256>>>(x);
    k_scores<<<dim3(Lc / 128, 4, Hc), 128>>>();
    k_out<<<dim3(Lc / 64, Bc), 128>>>(x, out);
}

// round 4
// speedup vs baseline: 1.4204x; 1.0311x over previous
#include <cuda_runtime.h>
#include <math.h>

// Problem constants
#define Lc 2048
#define Hc 8
#define Bc 8
#define Sc 128
#define HSc 1024

// ---------------- scratch (device globals) ----------------------------------
__device__ float d_eT[Hc * Lc];       // eT[h][d] = exp(W[d][h])
__device__ float d_zinv[Lc * Hc];     // 1/Z[l][h]
__device__ float d_q[Bc * HSc];
__device__ float d_u[Bc * HSc];
__device__ float d_G[Hc * Lc * Bc];   // G2[h][j][b]
__device__ float d_scores[Bc * Lc];

// f32x2 packed helpers (sm_100+)
__device__ __forceinline__ unsigned long long pack2(float v) {
    unsigned long long r;
    asm("mov.b64 %0, {%1, %1};" : "=l"(r) : "f"(v));
    return r;
}
__device__ __forceinline__ void fma2(unsigned long long& acc,
                                     unsigned long long a, unsigned long long b) {
    asm("fma.rn.f32x2 %0, %1, %2, %0;" : "+l"(acc) : "l"(a), "l"(b));
}
__device__ __forceinline__ float2 unpack2(unsigned long long v) {
    float2 r;
    asm("mov.b64 {%0, %1}, %2;" : "=f"(r.x), "=f"(r.y) : "l"(v));
    return r;
}

// ---------------- K0: init = scan (blocks 0..7) + zero (blocks 8..23) ------
__global__ void __launch_bounds__(1024) k_init(const float* __restrict__ W,
                                               float* __restrict__ out) {
    int blk = blockIdx.x;
    int t = threadIdx.x;
    if (blk < 8) {
        int h = blk;
        float v0 = expf(W[(2 * t) * Hc + h]);
        float v1 = expf(W[(2 * t + 1) * Hc + h]);
        float s = v0 + v1;
        unsigned lane = t & 31, wid = t >> 5;
        float x = s;
        #pragma unroll
        for (int o = 1; o < 32; o <<= 1) {
            float y = __shfl_up_sync(0xffffffffu, x, o);
            if (lane >= (unsigned)o) x += y;
        }
        __shared__ float wsum[32];
        if (lane == 31) wsum[wid] = x;
        __syncthreads();
        if (wid == 0) {
            float ws = wsum[lane];
            #pragma unroll
            for (int o = 1; o < 32; o <<= 1) {
                float y = __shfl_up_sync(0xffffffffu, ws, o);
                if (lane >= (unsigned)o) ws += y;
            }
            wsum[lane] = ws;
        }
        __syncthreads();
        float warp_off = (wid == 0) ? 0.f : wsum[wid - 1];
        float incl = x + warp_off;
        float excl = incl - s;
        d_eT[h * Lc + 2 * t]     = v0;
        d_eT[h * Lc + 2 * t + 1] = v1;
        d_zinv[(2 * t) * Hc + h]     = 1.f / (excl + v0);
        d_zinv[(2 * t + 1) * Hc + h] = 1.f / incl;
    } else {
        int i = (blk - 8) * 1024 + t;
        if (i < Bc * HSc) { d_q[i] = 0.f; d_u[i] = 0.f; }
        if (i < Bc * Lc)  d_scores[i] = 0.f;
        if (i < Bc * Sc)  out[i] = 0.f;
    }
}

// ---------------- K1: q_raw[b][h*S+s] = sum_j e[L-1-j,h] * x[b,j,s] --------
// grid (L/64, B), block 128 (thread = s). Batch-16 loads, f32x2 h-pairs.
__global__ void __launch_bounds__(128) k_q(const float* __restrict__ x) {
    int jbase = blockIdx.x * 64;
    int b = blockIdx.y;
    int s = threadIdx.x;
    __shared__ __align__(16) float se[64 * 8];   // se[jj][h]
    for (int i = s; i < 64 * 8; i += 128) {
        int jj = i >> 3, h = i & 7;
        se[i] = d_eT[h * Lc + (Lc - 1 - (jbase + jj))];
    }
    __syncthreads();

    unsigned long long a2[4] = {};
    const float* xp = x + ((size_t)b * Lc + jbase) * Sc + s;
    #pragma unroll
    for (int j0 = 0; j0 < 64; j0 += 16) {
        float xv[16];
        #pragma unroll
        for (int k = 0; k < 16; k++) xv[k] = xp[(j0 + k) * Sc];
        #pragma unroll
        for (int k = 0; k < 16; k++) {
            unsigned long long xd = pack2(xv[k]);
            ulonglong2 e01 = *(const ulonglong2*)&se[(j0 + k) * 8];
            ulonglong2 e23 = *(const ulonglong2*)&se[(j0 + k) * 8 + 4];
            fma2(a2[0], xd, e01.x);
            fma2(a2[1], xd, e01.y);
            fma2(a2[2], xd, e23.x);
            fma2(a2[3], xd, e23.y);
        }
    }
    #pragma unroll
    for (int p = 0; p < 4; p++) {
        float2 v = unpack2(a2[p]);
        atomicAdd(&d_q[b * HSc + (2 * p) * Sc + s], v.x);
        atomicAdd(&d_q[b * HSc + (2 * p + 1) * Sc + s], v.y);
    }
}

// ---------------- K2: u[b][e] = sum_d (q[b][d]*zinv_last) * A[d][e] --------
// grid (4 e-chunks, 64 d-chunks of 16), block 256 (thread = e). f32x2 b-pairs.
__global__ void __launch_bounds__(256) k_u(const float* __restrict__ A) {
    int ebase = blockIdx.x * 256;
    int dbase = blockIdx.y * 16;
    int t = threadIdx.x;
    __shared__ __align__(16) float sq[16 * 8];   // sq[dd][b]
    if (t < 128) {
        int dd = t >> 3, b = t & 7;
        int d = dbase + dd;
        sq[t] = d_q[b * HSc + d] * d_zinv[(Lc - 1) * Hc + (d >> 7)];
    }
    __syncthreads();

    int e = ebase + t;
    unsigned long long a2[4] = {};
    const float* Ap = A + (size_t)dbase * HSc + e;
    float av[16];
    #pragma unroll
    for (int k = 0; k < 16; k++) av[k] = Ap[k * HSc];
    #pragma unroll
    for (int k = 0; k < 16; k++) {
        unsigned long long ad = pack2(av[k]);
        ulonglong2 q01 = *(const ulonglong2*)&sq[k * 8];
        ulonglong2 q23 = *(const ulonglong2*)&sq[k * 8 + 4];
        fma2(a2[0], ad, q01.x);
        fma2(a2[1], ad, q01.y);
        fma2(a2[2], ad, q23.x);
        fma2(a2[3], ad, q23.y);
    }
    #pragma unroll
    for (int p = 0; p < 4; p++) {
        float2 v = unpack2(a2[p]);
        atomicAdd(&d_u[(2 * p) * HSc + e], v.x);
        atomicAdd(&d_u[(2 * p + 1) * HSc + e], v.y);
    }
}

// ---------------- K3: G2[h][j][b] = sum_s u[b][h*S+s] * x[b][j][s] ---------
// Tiled: block = 32 j x 8 h for one b. No shuffles; straight smem dot products
// with f32x2 packing over s-pairs.
__global__ void __launch_bounds__(256) k_G(const float* __restrict__ x) {
    int b = blockIdx.y;
    int jbase = blockIdx.x * 32;
    int t = threadIdx.x;
    __shared__ __align__(16) float su[8 * 132];
    __shared__ __align__(16) float sx[32 * 132];

    // load u[b] (1024 floats), row pitch 132
    for (int i = t; i < 1024; i += 256) {
        int h = i >> 7, s = i & 127;
        su[h * 132 + s] = d_u[b * HSc + i];
    }
    // load x tile (32 rows x 128), coalesced float4
    for (int idx = t; idx < 1024; idx += 256) {
        int row = idx >> 5, c4 = idx & 31;
        float4 v = *(const float4*)(x + ((size_t)b * Lc + jbase + row) * Sc + c4 * 4);
        *(float4*)&sx[row * 132 + c4 * 4] = v;
    }
    __syncthreads();

    int jl = t >> 3, h = t & 7;
    unsigned long long acc0 = 0, acc1 = 0;
    const float* sxr = &sx[jl * 132];
    const float* sur = &su[h * 132];
    #pragma unroll
    for (int s4 = 0; s4 < 32; s4++) {
        ulonglong2 xv = *(const ulonglong2*)(sxr + s4 * 4);
        ulonglong2 uv = *(const ulonglong2*)(sur + s4 * 4);
        fma2(acc0, xv.x, uv.x);
        fma2(acc1, xv.y, uv.y);
    }
    float2 p0 = unpack2(acc0);
    float2 p1 = unpack2(acc1);
    d_G[(size_t)h * Lc * Bc + (jbase + jl) * 8 + b] = (p0.x + p0.y) + (p1.x + p1.y);
}

// ---------------- K4: Toeplitz causal correlation (dominant) ---------------
// scores[b,l] += zinv[l,h] * sum_{j<=l} e[l-j,h] * G2[h][j][b]
__global__ void __launch_bounds__(128) k_scores() {
    int lt = blockIdx.x, jg = blockIdx.y, h = blockIdx.z;
    int jt0 = jg * 4;
    if (jt0 > lt) return;
    int jt1 = min(jt0 + 4, lt + 1);
    int lbase = lt * 128;
    int t = threadIdx.x, w = t >> 5, lane = t & 31;

    unsigned long long acc[4][4] = {};   // [k][b-pair]
    const float* eTh = d_eT + (size_t)h * Lc;
    const float* Gh  = d_G + (size_t)h * Lc * Bc;

    __shared__ __align__(16) float se[256];

    for (int jt = jt0; jt < jt1; jt++) {
        int D0 = lbase - jt * 128;          // >= 0
        __syncthreads();
        {
            int d0 = D0 - 127 + t, d1 = D0 + 1 + t;
            se[t] = (d0 >= 0) ? eTh[d0] : 0.f;
            se[t + 128] = (d1 >= 0) ? eTh[d1] : 0.f;
        }
        __syncthreads();

        int jb = jt * 128 + w * 32;
        int base_idx = 127 + lane - w * 32;
        #pragma unroll 2
        for (int jj = 0; jj < 32; jj++) {
            int j = jb + jj;
            ulonglong2 g01 = *(const ulonglong2*)(Gh + j * 8);
            ulonglong2 g23 = *(const ulonglong2*)(Gh + j * 8 + 4);
            int bi = base_idx - jj;
            #pragma unroll
            for (int k = 0; k < 4; k++) {
                unsigned long long ev = pack2(se[bi + 32 * k]);
                fma2(acc[k][0], ev, g01.x);
                fma2(acc[k][1], ev, g01.y);
                fma2(acc[k][2], ev, g23.x);
                fma2(acc[k][3], ev, g23.y);
            }
        }
    }

    __shared__ __align__(16) float sacc[4][128][8];
    #pragma unroll
    for (int k = 0; k < 4; k++) {
        float2 p0 = unpack2(acc[k][0]);
        float2 p1 = unpack2(acc[k][1]);
        float2 p2 = unpack2(acc[k][2]);
        float2 p3 = unpack2(acc[k][3]);
        *(float4*)&sacc[w][lane + 32 * k][0] = make_float4(p0.x, p0.y, p1.x, p1.y);
        *(float4*)&sacc[w][lane + 32 * k][4] = make_float4(p2.x, p2.y, p3.x, p3.y);
    }
    __syncthreads();

    int l = lbase + t;
    if (l < Lc - 1) {
        float zi = d_zinv[l * Hc + h];
        #pragma unroll
        for (int b = 0; b < 8; b++) {
            float v = sacc[0][t][b] + sacc[1][t][b] + sacc[2][t][b] + sacc[3][t][b];
            atomicAdd(&d_scores[b * Lc + l], v * zi);
        }
    }
}

// ---------------- K5: fused softmax stats + out ------------------------------
__global__ void __launch_bounds__(128) k_out(const float* __restrict__ x,
                                             float* __restrict__ out) {
    int lbase = blockIdx.x * 64;
    int b = blockIdx.y;
    int t = threadIdx.x;
    const float* sc = d_scores + b * Lc;

    __shared__ float red[128];
    float m = -1e30f;
    for (int l = t; l < Lc - 1; l += 128) m = fmaxf(m, sc[l]);
    red[t] = m; __syncthreads();
    for (int o = 64; o > 0; o >>= 1) {
        if (t < o) red[t] = fmaxf(red[t], red[t + o]);
        __syncthreads();
    }
    float M = red[0]; __syncthreads();
    float ss = 0.f;
    for (int l = t; l < Lc - 1; l += 128) ss += expf(sc[l] - M);
    red[t] = ss; __syncthreads();
    for (int o = 64; o > 0; o >>= 1) {
        if (t < o) red[t] += red[t + o];
        __syncthreads();
    }
    float sinv = 1.f / red[0];
    __syncthreads();

    __shared__ float wsm[64];
    if (t < 64) {
        int lg = lbase + t;
        wsm[t] = (lg < Lc - 1) ? expf(sc[lg] - M) * sinv : 0.f;
    }
    __syncthreads();

    float acc = 0.f;
    const float* xp = x + ((size_t)b * Lc + lbase) * Sc + t;
    #pragma unroll
    for (int j0 = 0; j0 < 64; j0 += 16) {
        float xv[16];
        #pragma unroll
        for (int k = 0; k < 16; k++) xv[k] = xp[(j0 + k) * Sc];
        #pragma unroll
        for (int k = 0; k < 16; k++) acc += wsm[j0 + k] * xv[k];
    }
    atomicAdd(&out[b * Sc + t], acc);
}

// ---------------- launch ----------------------------------------------------
extern "C" void kernel_launch(void* const* d_in, const int* in_sizes, int n_in,
                              void* d_out, int out_size) {
    const float *x = nullptr, *W = nullptr, *A = nullptr;
    for (int i = 0; i < n_in; i++) {
        if (in_sizes[i] == Bc * Lc * Sc)      x = (const float*)d_in[i];
        else if (in_sizes[i] == Lc * Hc)      W = (const float*)d_in[i];
        else if (in_sizes[i] == HSc * HSc)    A = (const float*)d_in[i];
    }
    float* out = (float*)d_out;

    k_init<<<24, 1024>>>(W, out);
    k_q<<<dim3(Lc / 64, Bc), 128>>>(x);
    k_u<<<dim3(HSc / 256, 64), 256>>>(A);
    k_G<<<dim3(Lc / 32, Bc), 256>>>(x);
    k_scores<<<dim3(Lc / 128, 4, Hc), 128>>>();
    k_out<<<dim3(Lc / 64, Bc), 128>>>(x, out);
}